// round 5
// baseline (speedup 1.0000x reference)
#include <cuda_runtime.h>

// ISNE embedding gather + masked-mean.
// Inputs (metadata order):
//   d_in[0] node_parameters  float32 [1000000, 128]
//   d_in[1] node_indices     int32   [16384]
//   d_in[2] pos_idx          int32   [16384, 32]
//   d_in[3] pos_len          int32   [16384]
//   d_in[4] neg_idx          int32   [16384, 32]
//   d_in[5] neg_len          int32   [16384]
// Output: concat(node_embeds, pos_embeds, neg_embeds) float32 [3*16384*128]
//
// One warp per output row. Lane l owns float4 #l of the 128-float row
// (32 lanes * 4 floats = 128). Neighbor indices are warp-register-resident
// and broadcast via shfl; mean loop unrolled x4 for MLP.

#define FULL_MASK 0xFFFFFFFFu
static constexpr int D4 = 32;  // float4s per 128-float row
static constexpr int K  = 32;  // max neighbors

__global__ __launch_bounds__(256) void isne_gather_mean_kernel(
    const float4* __restrict__ table,
    const int*    __restrict__ node_idx,
    const int*    __restrict__ pos_idx,
    const int*    __restrict__ pos_len,
    const int*    __restrict__ neg_idx,
    const int*    __restrict__ neg_len,
    float4*       __restrict__ out,
    int B)
{
    const int gwarp = (int)((blockIdx.x * blockDim.x + threadIdx.x) >> 5);
    const int lane  = threadIdx.x & 31;
    if (gwarp >= 3 * B) return;

    int task, b;
    if (gwarp < B)            { task = 0; b = gwarp;         }
    else if (gwarp < 2 * B)   { task = 1; b = gwarp - B;     }
    else                      { task = 2; b = gwarp - 2 * B; }

    if (task == 0) {
        // Plain gather: one row copy per warp.
        const int idx = __ldg(&node_idx[b]);
        const float4 v = __ldg(&table[(size_t)idx * D4 + lane]);
        out[(size_t)b * D4 + lane] = v;
        return;
    }

    const int* __restrict__ idxs = (task == 1) ? pos_idx : neg_idx;
    const int* __restrict__ lens = (task == 1) ? pos_len : neg_len;

    const int len   = __ldg(&lens[b]);
    const int myidx = __ldg(&idxs[(size_t)b * K + lane]);  // lane k holds idx[k]

    float4 acc = make_float4(0.f, 0.f, 0.f, 0.f);

    int k = 0;
    // x4 unroll: four independent row loads in flight before accumulation.
    for (; k + 4 <= len; k += 4) {
        const int i0 = __shfl_sync(FULL_MASK, myidx, k);
        const int i1 = __shfl_sync(FULL_MASK, myidx, k + 1);
        const int i2 = __shfl_sync(FULL_MASK, myidx, k + 2);
        const int i3 = __shfl_sync(FULL_MASK, myidx, k + 3);
        const float4 v0 = __ldg(&table[(size_t)i0 * D4 + lane]);
        const float4 v1 = __ldg(&table[(size_t)i1 * D4 + lane]);
        const float4 v2 = __ldg(&table[(size_t)i2 * D4 + lane]);
        const float4 v3 = __ldg(&table[(size_t)i3 * D4 + lane]);
        acc.x += (v0.x + v1.x) + (v2.x + v3.x);
        acc.y += (v0.y + v1.y) + (v2.y + v3.y);
        acc.z += (v0.z + v1.z) + (v2.z + v3.z);
        acc.w += (v0.w + v1.w) + (v2.w + v3.w);
    }
    for (; k < len; ++k) {
        const int i = __shfl_sync(FULL_MASK, myidx, k);
        const float4 v = __ldg(&table[(size_t)i * D4 + lane]);
        acc.x += v.x; acc.y += v.y; acc.z += v.z; acc.w += v.w;
    }

    const float scale = (len > 0) ? (1.0f / (float)len) : 0.0f;
    acc.x *= scale; acc.y *= scale; acc.z *= scale; acc.w *= scale;

    out[((size_t)task * B + b) * D4 + lane] = acc;
}

extern "C" void kernel_launch(void* const* d_in, const int* in_sizes, int n_in,
                              void* d_out, int out_size)
{
    const float4* table   = (const float4*)d_in[0];
    const int*    nidx    = (const int*)d_in[1];
    const int*    pidx    = (const int*)d_in[2];
    const int*    plen    = (const int*)d_in[3];
    const int*    gidx    = (const int*)d_in[4];
    const int*    glen    = (const int*)d_in[5];
    float4*       out     = (float4*)d_out;

    const int B = in_sizes[1];  // 16384 node indices

    const int total_threads = 3 * B * 32;  // one warp per output row
    const int threads = 256;
    const int blocks  = (total_threads + threads - 1) / threads;

    isne_gather_mean_kernel<<<blocks, threads>>>(
        table, nidx, pidx, plen, gidx, glen, out, B);
}